// round 16
// baseline (speedup 1.0000x reference)
#include <cuda_runtime.h>
#include <cuda_bf16.h>
#include <math.h>
#include <stdint.h>

#define BB 8
#define TT 4096
#define TP1 4097
#define DD 1024
#define KK 1024
#define MM (BB*TT)
#define NP 3072
#define BD (BB*DD)      // 8192
#define CS 128          // scan chunk size
#define CH 33           // ceil(4097/128)
#define NTILES 4096     // 16 nt x 256 bt
#define PGRID 148       // persistent CTAs (1 per SM)
#define NROWS (BB*TP1)  // 32776 cumsum rows
#define CNT_TARGET 256  // 16 warps x 16 nt tiles per bt

// ---------------- scratch (device globals) ----------------
__device__ __align__(16) unsigned char g_xh[(size_t)MM * KK * 2];
__device__ __align__(16) unsigned char g_xl[(size_t)MM * KK * 2];
__device__ __align__(16) unsigned char g_wh[(size_t)NP * KK * 2];
__device__ __align__(16) unsigned char g_wl[(size_t)NP * KK * 2];

__device__ float g_logf[(size_t)MM * DD];        // log_f [B,T,D]
__device__ float g_lv  [(size_t)BB * TP1 * DD];  // log_values [B,T+1,D]
__device__ float g_as  [(size_t)BB * TP1 * DD];  // a_star [B,T+1,D]

// 3-pass chunked-scan state
__device__ float g_cm[CH * BD];
__device__ float g_cs[CH * BD];
__device__ float g_pm[CH * BD];
__device__ float g_ps[CH * BD];

// gemm->cumsum handoff
__device__ int g_cnt[256];     // per-bt completion count (target 256)
__device__ int g_rowctr;       // cumsum row grab counter

// ---------------- math helpers ----------------
__device__ __forceinline__ float sp(float x) {
    return fmaxf(x, 0.0f) + log1pf(expf(-fabsf(x)));
}
__device__ __forceinline__ float log_g(float x) {
    return (x >= 0.0f) ? logf(x + 0.5f) : -sp(-x);
}

// ---------------- PTX helpers ----------------
__device__ __forceinline__ uint32_t smem_to_u32(const void* p) {
    uint32_t a;
    asm("{ .reg .u64 t; cvta.to.shared.u64 t, %1; cvt.u32.u64 %0, t; }"
        : "=r"(a) : "l"(p));
    return a;
}

#define MBARRIER_INIT(addr, cnt) \
    asm volatile("mbarrier.init.shared.b64 [%0], %1;" :: "r"((uint32_t)(addr)), "r"((uint32_t)(cnt)) : "memory")
#define MBARRIER_INVAL(addr) \
    asm volatile("mbarrier.inval.shared.b64 [%0];" :: "r"((uint32_t)(addr)) : "memory")
#define MBARRIER_EXPECT_TX(addr, bytes) \
    asm volatile("mbarrier.arrive.expect_tx.shared.b64 _, [%0], %1;" :: "r"((uint32_t)(addr)), "r"((uint32_t)(bytes)) : "memory")
#define MBARRIER_ARRIVE(addr) \
    asm volatile("mbarrier.arrive.shared.b64 _, [%0];" :: "r"((uint32_t)(addr)) : "memory")
#define FENCE_PROXY_ASYNC() \
    asm volatile("fence.proxy.async.shared::cta;" ::: "memory")

#define MBARRIER_WAIT_PARITY(mbar_smem_addr, phase_parity) do { \
    uint32_t _mbar = (uint32_t)(mbar_smem_addr); \
    uint32_t _parity = (uint32_t)(phase_parity); \
    uint32_t _done; \
    asm volatile("{\n\t.reg .pred p;\n\t" \
        "mbarrier.try_wait.parity.acquire.cta.shared::cta.b64 p, [%1], %2;\n\t" \
        "selp.b32 %0, 1, 0, p;\n\t}" \
        : "=r"(_done) : "r"(_mbar), "r"(_parity) : "memory"); \
    if (!_done) { \
        asm volatile("{\n\t.reg .pred P1;\n\t" \
            "WAIT_LOOP_%=:\n\t" \
            "mbarrier.try_wait.parity.acquire.cta.shared::cta.b64 P1, [%0], %1, 0x989680;\n\t" \
            "@P1 bra.uni WAIT_DONE_%=;\n\t" \
            "bra.uni WAIT_LOOP_%=;\n\t" \
            "WAIT_DONE_%=:\n\t}" \
            :: "r"(_mbar), "r"(_parity) : "memory"); \
    } \
} while(0)

#define MBARRIER_WAIT_PARITY_RELAXED(mbar_smem_addr, phase_parity) do { \
    uint32_t _mbar = (uint32_t)(mbar_smem_addr); \
    uint32_t _parity = (uint32_t)(phase_parity); \
    uint32_t _done; \
    asm volatile("{\n\t.reg .pred p;\n\t" \
        "mbarrier.try_wait.parity.relaxed.cta.shared::cta.b64 p, [%1], %2, 0x989680;\n\t" \
        "selp.b32 %0, 1, 0, p;\n\t}" \
        : "=r"(_done) : "r"(_mbar), "r"(_parity) : "memory"); \
    if (!_done) { \
        asm volatile("{\n\t.reg .pred P1;\n\t" \
            "WAIT_LOOP_%=:\n\t" \
            "mbarrier.try_wait.parity.relaxed.cta.shared::cta.b64 P1, [%0], %1, 0x989680;\n\t" \
            "@P1 bra.uni WAIT_DONE_%=;\n\t" \
            "bra.uni WAIT_LOOP_%=;\n\t" \
            "WAIT_DONE_%=:\n\t}" \
            :: "r"(_mbar), "r"(_parity) : "memory"); \
    } \
} while(0)

#define BULK_G2S(dst, src, bytes, mbar) \
    asm volatile("cp.async.bulk.shared::cluster.global.mbarrier::complete_tx::bytes [%0], [%1], %2, [%3];" \
        :: "r"((uint32_t)(dst)), "l"(src), "r"((uint32_t)(bytes)), "r"((uint32_t)(mbar)) : "memory")

__device__ __forceinline__ void ldsm4(uint32_t* r, uint32_t addr) {
    asm volatile("ldmatrix.sync.aligned.m8n8.x4.shared.b16 {%0,%1,%2,%3}, [%4];"
        : "=r"(r[0]), "=r"(r[1]), "=r"(r[2]), "=r"(r[3]) : "r"(addr));
}
__device__ __forceinline__ void mma16816(float* c, const uint32_t* a, const uint32_t* b) {
    asm volatile("mma.sync.aligned.m16n8k16.row.col.f32.bf16.bf16.f32 "
        "{%0,%1,%2,%3}, {%4,%5,%6,%7}, {%8,%9}, {%0,%1,%2,%3};"
        : "+f"(c[0]), "+f"(c[1]), "+f"(c[2]), "+f"(c[3])
        : "r"(a[0]), "r"(a[1]), "r"(a[2]), "r"(a[3]), "r"(b[0]), "r"(b[1]));
}

// =====================================================================
// shared cumsum-row machinery (used in gemm tail AND sweeper kernel)
// 512 threads per row; NAMED=true uses bar.sync 1,512 (gemm: producer
// warp excluded), NAMED=false uses __syncthreads (sweeper).
// =====================================================================
template<bool NAMED>
__device__ __forceinline__ void cbar() {
    if (NAMED) asm volatile("bar.sync 1, 512;" ::: "memory");
    else __syncthreads();
}

template<bool NAMED>
__device__ void cumsum_phase(int tid) {     // tid in [0,512)
    __shared__ int sh_row;
    __shared__ float wsum[16];
    const int lane = tid & 31, wp = tid >> 5;
    while (true) {
        if (tid == 0) sh_row = atomicAdd(&g_rowctr, 1);
        cbar<NAMED>();
        int r = sh_row;
        if (r >= NROWS) break;
        int b = r / TP1;
        int t = r - b * TP1;
        float2* dst = (float2*)(g_as + (size_t)r * DD);
        if (t == 0) {
            dst[tid] = make_float2(0.f, 0.f);
            continue;
        }
        int m = b * TT + t - 1;
        int bt = m >> 7;
        if (tid == 0) {
            while (((volatile int*)g_cnt)[bt] != CNT_TARGET) __nanosleep(64);
            __threadfence();
        }
        cbar<NAMED>();
        const float2* src = (const float2*)(g_logf + (size_t)m * DD);
        float2 v = src[tid];
        float s1 = v.x, s2 = v.x + v.y;
        float tsum = s2;
        #pragma unroll
        for (int off = 1; off < 32; off <<= 1) {
            float n = __shfl_up_sync(0xffffffffu, tsum, off);
            if (lane >= off) tsum += n;
        }
        if (lane == 31) wsum[wp] = tsum;
        cbar<NAMED>();
        float prev = tsum - s2;
        for (int w = 0; w < wp; w++) prev += wsum[w];
        dst[tid] = make_float2(prev + s1, prev + s2);
    }
}

__global__ void __launch_bounds__(512) cumsum_sweep_kernel() {
    cumsum_phase<false>(threadIdx.x);
}

// =====================================================================
// zero handoff counters (must run before gemm each replay)
// =====================================================================
__global__ void zero_ctrl_kernel() {
    int i = threadIdx.x;
    if (i < 256) g_cnt[i] = 0;
    if (i == 256) g_rowctr = 0;
}

// =====================================================================
// merged conversion: x-split + w-split + h0 in one launch
// =====================================================================
__device__ __forceinline__ void split4(const float4& v,
                                       unsigned long long& hh, unsigned long long& ll) {
    float f[4] = {v.x, v.y, v.z, v.w};
    unsigned long long h = 0, l = 0;
    #pragma unroll
    for (int i = 0; i < 4; i++) {
        __nv_bfloat16 hb = __float2bfloat16(f[i]);
        float hf = __bfloat162float(hb);
        __nv_bfloat16 lb = __float2bfloat16(f[i] - hf);
        h |= ((unsigned long long)__bfloat16_as_ushort(hb)) << (16 * i);
        l |= ((unsigned long long)__bfloat16_as_ushort(lb)) << (16 * i);
    }
    hh = h; ll = l;
}

__global__ void __launch_bounds__(256) convert_all_kernel(
    const float* __restrict__ x,
    const float* __restrict__ Wi, const float* __restrict__ Wf,
    const float* __restrict__ Wh, const float* __restrict__ h0) {
    int blk = blockIdx.x;
    int tid = threadIdx.x;
    if (blk < MM) {
        // ---- x convert ----
        int gid = blk * 256 + tid;
        int m  = gid >> 8;
        int k4 = gid & 255;
        float4 v = *(const float4*)(x + (size_t)m * KK + (k4 << 2));
        unsigned long long hh, ll;
        split4(v, hh, ll);
        int mt = m >> 7, r = m & 127;
        int k = k4 << 2, kc = k >> 6, c = k & 63;
        uint32_t boff = r * 128 + c * 2;
        uint32_t sw = boff ^ ((boff >> 3) & 0x70);
        size_t tb = ((size_t)(mt * 16 + kc)) << 14;
        *(unsigned long long*)(g_xh + tb + sw) = hh;
        *(unsigned long long*)(g_xl + tb + sw) = ll;
    } else if (blk < MM + 3072) {
        // ---- w convert ----
        int gid = (blk - MM) * 256 + tid;
        int mat = gid >> 18;
        int rem = gid & 262143;
        int d  = rem >> 8;
        int k4 = rem & 255;
        const float* W = (mat == 0) ? Wi : ((mat == 1) ? Wf : Wh);
        float4 v = *(const float4*)(W + (size_t)d * KK + (k4 << 2));
        unsigned long long hh, ll;
        split4(v, hh, ll);
        int nt = d >> 6;
        int r  = ((d >> 3) & 7) * 24 + mat * 8 + (d & 7);
        int k = k4 << 2, kc = k >> 6, c = k & 63;
        uint32_t boff = r * 128 + c * 2;
        uint32_t sw = boff ^ ((boff >> 3) & 0x70);
        size_t tb = (size_t)(nt * 16 + kc) * 24576;
        *(unsigned long long*)(g_wh + tb + sw) = hh;
        *(unsigned long long*)(g_wl + tb + sw) = ll;
    } else {
        // ---- h0 -> log_values[:,0,:] ----
        int i = (blk - MM - 3072) * 256 + tid;   // < BB*DD
        int b = i >> 10;
        int d = i & (DD - 1);
        g_lv[(size_t)b * TP1 * DD + d] = log_g(h0[i]);
    }
}

// =====================================================================
// PERSISTENT HMMA GEMM + cumsum tail phase.
// =====================================================================
#define STG_BYTES 81920
#define OFF_AH 0
#define OFF_AL 16384
#define OFF_BH 32768
#define OFF_BL 57344
#define SMEM_TILES 1024

__global__ void __launch_bounds__(544, 1)
gemm_kernel(const float* __restrict__ pbi, const float* __restrict__ pbf,
            const float* __restrict__ pbh) {
    extern __shared__ __align__(1024) unsigned char smem[];
    uint32_t sb = smem_to_u32(smem);
    const int tid = threadIdx.x;
    const int wid = tid >> 5, lane = tid & 31;
    const int bid = blockIdx.x;

    if (tid == 0) {
        MBARRIER_INIT(sb + 0,  1);
        MBARRIER_INIT(sb + 8,  1);
        MBARRIER_INIT(sb + 16, 16);
        MBARRIER_INIT(sb + 24, 16);
        FENCE_PROXY_ASYNC();
    }
    __syncthreads();

    if (wid == 16) {
        if (lane == 0) {
            uint32_t gcc = 0;
            #pragma unroll 1
            for (int tile = bid; tile < NTILES; tile += PGRID) {
                const int nt = tile & 15;
                const int bt = tile >> 4;
                #pragma unroll 1
                for (int c = 0; c < 16; c++, gcc++) {
                    const int s = (int)(gcc & 1u);
                    const uint32_t eph = ((gcc >> 1) & 1u) ^ 1u;
                    MBARRIER_WAIT_PARITY_RELAXED(sb + 16 + s * 8, eph);
                    uint32_t fb = sb + s * 8;
                    uint32_t dst = sb + SMEM_TILES + s * STG_BYTES;
                    const unsigned char* ah = g_xh + (((size_t)(bt * 16 + c)) << 14);
                    const unsigned char* al = g_xl + (((size_t)(bt * 16 + c)) << 14);
                    const unsigned char* bh_ = g_wh + (size_t)(nt * 16 + c) * 24576;
                    const unsigned char* bl_ = g_wl + (size_t)(nt * 16 + c) * 24576;
                    MBARRIER_EXPECT_TX(fb, STG_BYTES);
                    BULK_G2S(dst + OFF_AH, ah, 16384, fb);
                    BULK_G2S(dst + OFF_AL, al, 16384, fb);
                    BULK_G2S(dst + OFF_BH, bh_, 24576, fb);
                    BULK_G2S(dst + OFF_BL, bl_, 24576, fb);
                }
            }
        }
    } else {
        const int warpM = wid & 3;
        const int warpN = wid >> 2;
        const int kofs = warpN;
        const int g = lane >> 3;
        const uint32_t xorv = (uint32_t)((lane & 7) << 4);
        uint32_t aoff[2], boff[3];
        #pragma unroll
        for (int mt = 0; mt < 2; mt++) {
            int row = warpM * 32 + mt * 16 + (g & 1) * 8 + (lane & 7);
            aoff[mt] = (uint32_t)(row * 128);
        }
        const uint32_t acol16 = (uint32_t)((g >> 1) * 16);
        #pragma unroll
        for (int p = 0; p < 3; p++) {
            int row = warpN * 48 + p * 16 + (g >> 1) * 8 + (lane & 7);
            boff[p] = (uint32_t)(row * 128);
        }
        const uint32_t bcol16 = (uint32_t)((g & 1) * 16);

        uint32_t gcc = 0;
        #pragma unroll 1
        for (int tile = bid; tile < NTILES; tile += PGRID) {
            const int nt = tile & 15;
            const int bt = tile >> 4;

            float acc[2][6][4];
            #pragma unroll
            for (int mt = 0; mt < 2; mt++)
                #pragma unroll
                for (int n8 = 0; n8 < 6; n8++)
                    #pragma unroll
                    for (int e = 0; e < 4; e++)
                        acc[mt][n8][e] = 0.0f;

            #pragma unroll 1
            for (int c = 0; c < 16; c++, gcc++) {
                const int s = (int)(gcc & 1u);
                const uint32_t ph = (gcc >> 1) & 1u;
                MBARRIER_WAIT_PARITY(sb + s * 8, ph);
                const uint32_t st = sb + SMEM_TILES + s * STG_BYTES;

                #pragma unroll
                for (int ks0 = 0; ks0 < 4; ks0++) {
                    const int ks = (ks0 + kofs) & 3;
                    const uint32_t ca = (uint32_t)(ks * 32);
                    const uint32_t cswA = (ca + acol16) ^ xorv;
                    const uint32_t cswB = (ca + bcol16) ^ xorv;
                    uint32_t Ah[2][4], Al[2][4], Bh[3][4], Bl[3][4];
                    #pragma unroll
                    for (int mt = 0; mt < 2; mt++) {
                        ldsm4(Ah[mt], st + OFF_AH + aoff[mt] + cswA);
                        ldsm4(Al[mt], st + OFF_AL + aoff[mt] + cswA);
                    }
                    #pragma unroll
                    for (int p = 0; p < 3; p++) {
                        ldsm4(Bh[p], st + OFF_BH + boff[p] + cswB);
                        ldsm4(Bl[p], st + OFF_BL + boff[p] + cswB);
                    }
                    #pragma unroll
                    for (int mt = 0; mt < 2; mt++)
                        #pragma unroll
                        for (int n8 = 0; n8 < 6; n8++)
                            mma16816(acc[mt][n8], Ah[mt], &Bh[n8 >> 1][(n8 & 1) * 2]);
                    #pragma unroll
                    for (int mt = 0; mt < 2; mt++)
                        #pragma unroll
                        for (int n8 = 0; n8 < 6; n8++)
                            mma16816(acc[mt][n8], Al[mt], &Bh[n8 >> 1][(n8 & 1) * 2]);
                    #pragma unroll
                    for (int mt = 0; mt < 2; mt++)
                        #pragma unroll
                        for (int n8 = 0; n8 < 6; n8++)
                            mma16816(acc[mt][n8], Ah[mt], &Bl[n8 >> 1][(n8 & 1) * 2]);
                }
                if (lane == 0) MBARRIER_ARRIVE(sb + 16 + s * 8);
            }

            // -------- fused gate epilogue --------
            #pragma unroll
            for (int gg = 0; gg < 2; gg++) {
                const int d0 = nt * 64 + (warpN * 2 + gg) * 8 + (lane & 3) * 2;
                const float bi0 = pbi[d0], bi1 = pbi[d0 + 1];
                const float bf0 = pbf[d0], bf1 = pbf[d0 + 1];
                const float bh0 = pbh[d0], bh1 = pbh[d0 + 1];
                #pragma unroll
                for (int mt = 0; mt < 2; mt++) {
                    const int mrow0 = bt * 128 + warpM * 32 + mt * 16 + (lane >> 2);
                    const float* zi = acc[mt][3 * gg + 0];
                    const float* zf = acc[mt][3 * gg + 1];
                    const float* zh = acc[mt][3 * gg + 2];
                    #pragma unroll
                    for (int e = 0; e < 2; e++) {
                        const int m = mrow0 + e * 8;
                        const int b = m >> 12;
                        float z_i0 = zi[2 * e] + bi0, z_i1 = zi[2 * e + 1] + bi1;
                        float z_f0 = zf[2 * e] + bf0, z_f1 = zf[2 * e + 1] + bf1;
                        float z_h0 = zh[2 * e] + bh0, z_h1 = zh[2 * e + 1] + bh1;
                        float u0 = __expf(-z_i0), v0 = __expf(-z_f0);
                        float u1 = __expf(-z_i1), v1 = __expf(-z_f1);
                        float lgD0 = __logf(2.0f + u0 + v0);
                        float lgD1 = __logf(2.0f + u1 + v1);
                        float lf0 = __logf(1.0f + u0) - lgD0;
                        float lf1 = __logf(1.0f + u1) - lgD1;
                        float li0 = __logf(1.0f + v0) - lgD0;
                        float li1 = __logf(1.0f + v1) - lgD1;
                        float lg0 = (z_h0 >= 0.0f) ? __logf(z_h0 + 0.5f)
                                                   : (z_h0 - __logf(1.0f + __expf(z_h0)));
                        float lg1 = (z_h1 >= 0.0f) ? __logf(z_h1 + 0.5f)
                                                   : (z_h1 - __logf(1.0f + __expf(z_h1)));
                        float lv0 = li0 + lg0;
                        float lv1 = li1 + lg1;
                        *(float2*)(g_logf + (size_t)m * DD + d0) = make_float2(lf0, lf1);
                        *(float2*)(g_lv + (size_t)(m + b + 1) * DD + d0) = make_float2(lv0, lv1);
                    }
                }
            }

            // publish this (nt,bt) tile: per-warp release (16 per tile)
            __threadfence();
            __syncwarp();
            if (lane == 0) atomicAdd(&g_cnt[bt], 1);
        }

        // -------- cumsum tail phase: soak up idle-tail capacity --------
        cumsum_phase<true>(tid);
    }

    __syncthreads();
    if (tid == 0) {
        MBARRIER_INVAL(sb + 0);
        MBARRIER_INVAL(sb + 8);
        MBARRIER_INVAL(sb + 16);
        MBARRIER_INVAL(sb + 24);
    }
}

// =====================================================================
// chunked logcumsumexp over time (3 passes -- proven round-12 config)
// =====================================================================
__global__ void __launch_bounds__(256) scan_a_kernel() {
    int gid = blockIdx.x * 256 + threadIdx.x;   // < CH*BD
    int c  = gid >> 13;
    int bd = gid & (BD - 1);
    int b = bd >> 10, d = bd & (DD - 1);
    int t0 = c * CS;
    int t1 = t0 + CS; if (t1 > TP1) t1 = TP1;
    size_t base = (size_t)b * TP1 * DD + d;

    float m = -INFINITY, s = 0.0f;
    for (int t = t0; t < t1; t++) {
        size_t idx = base + (size_t)t * DD;
        float v  = g_lv[idx] - g_as[idx];
        float mn = fmaxf(m, v);
        s = s * __expf(m - mn) + __expf(v - mn);
        m = mn;
    }
    g_cm[gid] = m;
    g_cs[gid] = s;
}

__global__ void __launch_bounds__(256) scan_b_kernel() {
    int bd = blockIdx.x * 256 + threadIdx.x;    // < BD
    float M = -INFINITY, S = 0.0f;
    #pragma unroll 1
    for (int c = 0; c < CH; c++) {
        int i = c * BD + bd;
        g_pm[i] = M;
        g_ps[i] = S;
        float m = g_cm[i], s = g_cs[i];
        float mn = fmaxf(M, m);
        S = S * __expf(M - mn) + s * __expf(m - mn);
        M = mn;
    }
}

__global__ void __launch_bounds__(256) scan_c_kernel(float* __restrict__ out) {
    int gid = blockIdx.x * 256 + threadIdx.x;   // < CH*BD
    int c  = gid >> 13;
    int bd = gid & (BD - 1);
    int b = bd >> 10, d = bd & (DD - 1);
    int t0 = c * CS;
    int t1 = t0 + CS; if (t1 > TP1) t1 = TP1;
    size_t base = (size_t)b * TP1 * DD + d;

    float m = g_pm[gid];
    float s = g_ps[gid];
    for (int t = t0; t < t1; t++) {
        size_t idx = base + (size_t)t * DD;
        float a  = g_as[idx];
        float v  = g_lv[idx] - a;
        float mn = fmaxf(m, v);
        s = s * __expf(m - mn) + __expf(v - mn);
        m = mn;
        out[idx] = __expf(a + m + __logf(s));
    }
}

// =====================================================================
extern "C" void kernel_launch(void* const* d_in, const int* in_sizes, int n_in,
                              void* d_out, int out_size)
{
    const float* x  = (const float*)d_in[0];
    const float* h0 = (const float*)d_in[1];
    const float* Wi = (const float*)d_in[2];
    const float* bi = (const float*)d_in[3];
    const float* Wf = (const float*)d_in[4];
    const float* bf = (const float*)d_in[5];
    const float* Wh = (const float*)d_in[6];
    const float* bh = (const float*)d_in[7];
    float* out = (float*)d_out;
    (void)in_sizes; (void)n_in; (void)out_size;

    const int smem_bytes = SMEM_TILES + 2 * STG_BYTES;   // 164864
    cudaFuncSetAttribute(gemm_kernel, cudaFuncAttributeMaxDynamicSharedMemorySize, smem_bytes);

    zero_ctrl_kernel<<<1, 288>>>();
    convert_all_kernel<<<MM + 3072 + (BB * DD) / 256, 256>>>(x, Wi, Wf, Wh, h0);
    gemm_kernel<<<PGRID, 544, smem_bytes>>>(bi, bf, bh);
    cumsum_sweep_kernel<<<2 * PGRID, 512>>>();
    scan_a_kernel<<<(CH * BD) / 256, 256>>>();
    scan_b_kernel<<<BD / 256, 256>>>();
    scan_c_kernel<<<(CH * BD) / 256, 256>>>(out);
}

// round 17
// speedup vs baseline: 1.2466x; 1.2466x over previous
#include <cuda_runtime.h>
#include <cuda_bf16.h>
#include <math.h>
#include <stdint.h>

#define BB 8
#define TT 4096
#define TP1 4097
#define DD 1024
#define KK 1024
#define MM (BB*TT)
#define NP 3072
#define BD (BB*DD)      // 8192
#define CS 128          // scan chunk size
#define CH 33           // ceil(4097/128)
#define NTILES 4096     // 16 nt x 256 bt
#define PGRID 148       // persistent CTAs (1 per SM)

// ---------------- scratch (device globals) ----------------
__device__ __align__(16) unsigned char g_xh[(size_t)MM * KK * 2];
__device__ __align__(16) unsigned char g_xl[(size_t)MM * KK * 2];
__device__ __align__(16) unsigned char g_wh[(size_t)NP * KK * 2];
__device__ __align__(16) unsigned char g_wl[(size_t)NP * KK * 2];

__device__ float g_logf[(size_t)MM * DD];        // log_f [B,T,D]
__device__ float g_lv  [(size_t)BB * TP1 * DD];  // log_values [B,T+1,D]
__device__ float g_as  [(size_t)BB * TP1 * DD];  // a_star [B,T+1,D]

// 3-pass chunked-scan state
__device__ float g_cm[CH * BD];
__device__ float g_cs[CH * BD];
__device__ float g_pm[CH * BD];
__device__ float g_ps[CH * BD];

// ---------------- math helpers ----------------
__device__ __forceinline__ float sp(float x) {
    return fmaxf(x, 0.0f) + log1pf(expf(-fabsf(x)));
}
__device__ __forceinline__ float log_g(float x) {
    return (x >= 0.0f) ? logf(x + 0.5f) : -sp(-x);
}

// ---------------- PTX helpers ----------------
__device__ __forceinline__ uint32_t smem_to_u32(const void* p) {
    uint32_t a;
    asm("{ .reg .u64 t; cvta.to.shared.u64 t, %1; cvt.u32.u64 %0, t; }"
        : "=r"(a) : "l"(p));
    return a;
}

#define MBARRIER_INIT(addr, cnt) \
    asm volatile("mbarrier.init.shared.b64 [%0], %1;" :: "r"((uint32_t)(addr)), "r"((uint32_t)(cnt)) : "memory")
#define MBARRIER_INVAL(addr) \
    asm volatile("mbarrier.inval.shared.b64 [%0];" :: "r"((uint32_t)(addr)) : "memory")
#define MBARRIER_EXPECT_TX(addr, bytes) \
    asm volatile("mbarrier.arrive.expect_tx.shared.b64 _, [%0], %1;" :: "r"((uint32_t)(addr)), "r"((uint32_t)(bytes)) : "memory")
#define MBARRIER_ARRIVE(addr) \
    asm volatile("mbarrier.arrive.shared.b64 _, [%0];" :: "r"((uint32_t)(addr)) : "memory")
#define FENCE_PROXY_ASYNC() \
    asm volatile("fence.proxy.async.shared::cta;" ::: "memory")

#define MBARRIER_WAIT_PARITY(mbar_smem_addr, phase_parity) do { \
    uint32_t _mbar = (uint32_t)(mbar_smem_addr); \
    uint32_t _parity = (uint32_t)(phase_parity); \
    uint32_t _done; \
    asm volatile("{\n\t.reg .pred p;\n\t" \
        "mbarrier.try_wait.parity.acquire.cta.shared::cta.b64 p, [%1], %2;\n\t" \
        "selp.b32 %0, 1, 0, p;\n\t}" \
        : "=r"(_done) : "r"(_mbar), "r"(_parity) : "memory"); \
    if (!_done) { \
        asm volatile("{\n\t.reg .pred P1;\n\t" \
            "WAIT_LOOP_%=:\n\t" \
            "mbarrier.try_wait.parity.acquire.cta.shared::cta.b64 P1, [%0], %1, 0x989680;\n\t" \
            "@P1 bra.uni WAIT_DONE_%=;\n\t" \
            "bra.uni WAIT_LOOP_%=;\n\t" \
            "WAIT_DONE_%=:\n\t}" \
            :: "r"(_mbar), "r"(_parity) : "memory"); \
    } \
} while(0)

#define MBARRIER_WAIT_PARITY_RELAXED(mbar_smem_addr, phase_parity) do { \
    uint32_t _mbar = (uint32_t)(mbar_smem_addr); \
    uint32_t _parity = (uint32_t)(phase_parity); \
    uint32_t _done; \
    asm volatile("{\n\t.reg .pred p;\n\t" \
        "mbarrier.try_wait.parity.relaxed.cta.shared::cta.b64 p, [%1], %2, 0x989680;\n\t" \
        "selp.b32 %0, 1, 0, p;\n\t}" \
        : "=r"(_done) : "r"(_mbar), "r"(_parity) : "memory"); \
    if (!_done) { \
        asm volatile("{\n\t.reg .pred P1;\n\t" \
            "WAIT_LOOP_%=:\n\t" \
            "mbarrier.try_wait.parity.relaxed.cta.shared::cta.b64 P1, [%0], %1, 0x989680;\n\t" \
            "@P1 bra.uni WAIT_DONE_%=;\n\t" \
            "bra.uni WAIT_LOOP_%=;\n\t" \
            "WAIT_DONE_%=:\n\t}" \
            :: "r"(_mbar), "r"(_parity) : "memory"); \
    } \
} while(0)

#define BULK_G2S(dst, src, bytes, mbar) \
    asm volatile("cp.async.bulk.shared::cluster.global.mbarrier::complete_tx::bytes [%0], [%1], %2, [%3];" \
        :: "r"((uint32_t)(dst)), "l"(src), "r"((uint32_t)(bytes)), "r"((uint32_t)(mbar)) : "memory")

__device__ __forceinline__ void ldsm4(uint32_t* r, uint32_t addr) {
    asm volatile("ldmatrix.sync.aligned.m8n8.x4.shared.b16 {%0,%1,%2,%3}, [%4];"
        : "=r"(r[0]), "=r"(r[1]), "=r"(r[2]), "=r"(r[3]) : "r"(addr));
}
__device__ __forceinline__ void mma16816(float* c, const uint32_t* a, const uint32_t* b) {
    asm volatile("mma.sync.aligned.m16n8k16.row.col.f32.bf16.bf16.f32 "
        "{%0,%1,%2,%3}, {%4,%5,%6,%7}, {%8,%9}, {%0,%1,%2,%3};"
        : "+f"(c[0]), "+f"(c[1]), "+f"(c[2]), "+f"(c[3])
        : "r"(a[0]), "r"(a[1]), "r"(a[2]), "r"(a[3]), "r"(b[0]), "r"(b[1]));
}

// =====================================================================
// merged conversion: x-split + w-split + h0 in one launch
// =====================================================================
__device__ __forceinline__ void split4(const float4& v,
                                       unsigned long long& hh, unsigned long long& ll) {
    float f[4] = {v.x, v.y, v.z, v.w};
    unsigned long long h = 0, l = 0;
    #pragma unroll
    for (int i = 0; i < 4; i++) {
        __nv_bfloat16 hb = __float2bfloat16(f[i]);
        float hf = __bfloat162float(hb);
        __nv_bfloat16 lb = __float2bfloat16(f[i] - hf);
        h |= ((unsigned long long)__bfloat16_as_ushort(hb)) << (16 * i);
        l |= ((unsigned long long)__bfloat16_as_ushort(lb)) << (16 * i);
    }
    hh = h; ll = l;
}

__global__ void __launch_bounds__(256) convert_all_kernel(
    const float* __restrict__ x,
    const float* __restrict__ Wi, const float* __restrict__ Wf,
    const float* __restrict__ Wh, const float* __restrict__ h0) {
    int blk = blockIdx.x;
    int tid = threadIdx.x;
    if (blk < MM) {
        // ---- x convert ----
        int gid = blk * 256 + tid;
        int m  = gid >> 8;
        int k4 = gid & 255;
        float4 v = *(const float4*)(x + (size_t)m * KK + (k4 << 2));
        unsigned long long hh, ll;
        split4(v, hh, ll);
        int mt = m >> 7, r = m & 127;
        int k = k4 << 2, kc = k >> 6, c = k & 63;
        uint32_t boff = r * 128 + c * 2;
        uint32_t sw = boff ^ ((boff >> 3) & 0x70);
        size_t tb = ((size_t)(mt * 16 + kc)) << 14;
        *(unsigned long long*)(g_xh + tb + sw) = hh;
        *(unsigned long long*)(g_xl + tb + sw) = ll;
    } else if (blk < MM + 3072) {
        // ---- w convert ----
        int gid = (blk - MM) * 256 + tid;
        int mat = gid >> 18;
        int rem = gid & 262143;
        int d  = rem >> 8;
        int k4 = rem & 255;
        const float* W = (mat == 0) ? Wi : ((mat == 1) ? Wf : Wh);
        float4 v = *(const float4*)(W + (size_t)d * KK + (k4 << 2));
        unsigned long long hh, ll;
        split4(v, hh, ll);
        int nt = d >> 6;
        int r  = ((d >> 3) & 7) * 24 + mat * 8 + (d & 7);
        int k = k4 << 2, kc = k >> 6, c = k & 63;
        uint32_t boff = r * 128 + c * 2;
        uint32_t sw = boff ^ ((boff >> 3) & 0x70);
        size_t tb = (size_t)(nt * 16 + kc) * 24576;
        *(unsigned long long*)(g_wh + tb + sw) = hh;
        *(unsigned long long*)(g_wl + tb + sw) = ll;
    } else {
        // ---- h0 -> log_values[:,0,:] ----
        int i = (blk - MM - 3072) * 256 + tid;   // < BB*DD
        int b = i >> 10;
        int d = i & (DD - 1);
        g_lv[(size_t)b * TP1 * DD + d] = log_g(h0[i]);
    }
}

// =====================================================================
// PERSISTENT HMMA GEMM (round-12 proven): 148 CTAs x 4096 tiles.
// 16 compute warps (4M x 4N, warp tile 32x48) + producer warp 16.
// =====================================================================
#define STG_BYTES 81920
#define OFF_AH 0
#define OFF_AL 16384
#define OFF_BH 32768
#define OFF_BL 57344
#define SMEM_TILES 1024

__global__ void __launch_bounds__(544, 1)
gemm_kernel(const float* __restrict__ pbi, const float* __restrict__ pbf,
            const float* __restrict__ pbh) {
    extern __shared__ __align__(1024) unsigned char smem[];
    uint32_t sb = smem_to_u32(smem);
    const int tid = threadIdx.x;
    const int wid = tid >> 5, lane = tid & 31;
    const int bid = blockIdx.x;

    if (tid == 0) {
        MBARRIER_INIT(sb + 0,  1);
        MBARRIER_INIT(sb + 8,  1);
        MBARRIER_INIT(sb + 16, 16);
        MBARRIER_INIT(sb + 24, 16);
        FENCE_PROXY_ASYNC();
    }
    __syncthreads();

    if (wid == 16) {
        if (lane == 0) {
            uint32_t gcc = 0;
            #pragma unroll 1
            for (int tile = bid; tile < NTILES; tile += PGRID) {
                const int nt = tile & 15;
                const int bt = tile >> 4;
                #pragma unroll 1
                for (int c = 0; c < 16; c++, gcc++) {
                    const int s = (int)(gcc & 1u);
                    const uint32_t eph = ((gcc >> 1) & 1u) ^ 1u;
                    MBARRIER_WAIT_PARITY_RELAXED(sb + 16 + s * 8, eph);
                    uint32_t fb = sb + s * 8;
                    uint32_t dst = sb + SMEM_TILES + s * STG_BYTES;
                    const unsigned char* ah = g_xh + (((size_t)(bt * 16 + c)) << 14);
                    const unsigned char* al = g_xl + (((size_t)(bt * 16 + c)) << 14);
                    const unsigned char* bh_ = g_wh + (size_t)(nt * 16 + c) * 24576;
                    const unsigned char* bl_ = g_wl + (size_t)(nt * 16 + c) * 24576;
                    MBARRIER_EXPECT_TX(fb, STG_BYTES);
                    BULK_G2S(dst + OFF_AH, ah, 16384, fb);
                    BULK_G2S(dst + OFF_AL, al, 16384, fb);
                    BULK_G2S(dst + OFF_BH, bh_, 24576, fb);
                    BULK_G2S(dst + OFF_BL, bl_, 24576, fb);
                }
            }
        }
    } else {
        const int warpM = wid & 3;
        const int warpN = wid >> 2;
        const int kofs = warpN;
        const int g = lane >> 3;
        const uint32_t xorv = (uint32_t)((lane & 7) << 4);
        uint32_t aoff[2], boff[3];
        #pragma unroll
        for (int mt = 0; mt < 2; mt++) {
            int row = warpM * 32 + mt * 16 + (g & 1) * 8 + (lane & 7);
            aoff[mt] = (uint32_t)(row * 128);
        }
        const uint32_t acol16 = (uint32_t)((g >> 1) * 16);
        #pragma unroll
        for (int p = 0; p < 3; p++) {
            int row = warpN * 48 + p * 16 + (g >> 1) * 8 + (lane & 7);
            boff[p] = (uint32_t)(row * 128);
        }
        const uint32_t bcol16 = (uint32_t)((g & 1) * 16);

        uint32_t gcc = 0;
        #pragma unroll 1
        for (int tile = bid; tile < NTILES; tile += PGRID) {
            const int nt = tile & 15;
            const int bt = tile >> 4;

            float acc[2][6][4];
            #pragma unroll
            for (int mt = 0; mt < 2; mt++)
                #pragma unroll
                for (int n8 = 0; n8 < 6; n8++)
                    #pragma unroll
                    for (int e = 0; e < 4; e++)
                        acc[mt][n8][e] = 0.0f;

            #pragma unroll 1
            for (int c = 0; c < 16; c++, gcc++) {
                const int s = (int)(gcc & 1u);
                const uint32_t ph = (gcc >> 1) & 1u;
                MBARRIER_WAIT_PARITY(sb + s * 8, ph);
                const uint32_t st = sb + SMEM_TILES + s * STG_BYTES;

                #pragma unroll
                for (int ks0 = 0; ks0 < 4; ks0++) {
                    const int ks = (ks0 + kofs) & 3;
                    const uint32_t ca = (uint32_t)(ks * 32);
                    const uint32_t cswA = (ca + acol16) ^ xorv;
                    const uint32_t cswB = (ca + bcol16) ^ xorv;
                    uint32_t Ah[2][4], Al[2][4], Bh[3][4], Bl[3][4];
                    #pragma unroll
                    for (int mt = 0; mt < 2; mt++) {
                        ldsm4(Ah[mt], st + OFF_AH + aoff[mt] + cswA);
                        ldsm4(Al[mt], st + OFF_AL + aoff[mt] + cswA);
                    }
                    #pragma unroll
                    for (int p = 0; p < 3; p++) {
                        ldsm4(Bh[p], st + OFF_BH + boff[p] + cswB);
                        ldsm4(Bl[p], st + OFF_BL + boff[p] + cswB);
                    }
                    #pragma unroll
                    for (int mt = 0; mt < 2; mt++)
                        #pragma unroll
                        for (int n8 = 0; n8 < 6; n8++)
                            mma16816(acc[mt][n8], Ah[mt], &Bh[n8 >> 1][(n8 & 1) * 2]);
                    #pragma unroll
                    for (int mt = 0; mt < 2; mt++)
                        #pragma unroll
                        for (int n8 = 0; n8 < 6; n8++)
                            mma16816(acc[mt][n8], Al[mt], &Bh[n8 >> 1][(n8 & 1) * 2]);
                    #pragma unroll
                    for (int mt = 0; mt < 2; mt++)
                        #pragma unroll
                        for (int n8 = 0; n8 < 6; n8++)
                            mma16816(acc[mt][n8], Ah[mt], &Bl[n8 >> 1][(n8 & 1) * 2]);
                }
                if (lane == 0) MBARRIER_ARRIVE(sb + 16 + s * 8);
            }

            // -------- fused gate epilogue --------
            #pragma unroll
            for (int gg = 0; gg < 2; gg++) {
                const int d0 = nt * 64 + (warpN * 2 + gg) * 8 + (lane & 3) * 2;
                const float bi0 = pbi[d0], bi1 = pbi[d0 + 1];
                const float bf0 = pbf[d0], bf1 = pbf[d0 + 1];
                const float bh0 = pbh[d0], bh1 = pbh[d0 + 1];
                #pragma unroll
                for (int mt = 0; mt < 2; mt++) {
                    const int mrow0 = bt * 128 + warpM * 32 + mt * 16 + (lane >> 2);
                    const float* zi = acc[mt][3 * gg + 0];
                    const float* zf = acc[mt][3 * gg + 1];
                    const float* zh = acc[mt][3 * gg + 2];
                    #pragma unroll
                    for (int e = 0; e < 2; e++) {
                        const int m = mrow0 + e * 8;
                        const int b = m >> 12;
                        float z_i0 = zi[2 * e] + bi0, z_i1 = zi[2 * e + 1] + bi1;
                        float z_f0 = zf[2 * e] + bf0, z_f1 = zf[2 * e + 1] + bf1;
                        float z_h0 = zh[2 * e] + bh0, z_h1 = zh[2 * e + 1] + bh1;
                        float u0 = __expf(-z_i0), v0 = __expf(-z_f0);
                        float u1 = __expf(-z_i1), v1 = __expf(-z_f1);
                        float lgD0 = __logf(2.0f + u0 + v0);
                        float lgD1 = __logf(2.0f + u1 + v1);
                        float lf0 = __logf(1.0f + u0) - lgD0;
                        float lf1 = __logf(1.0f + u1) - lgD1;
                        float li0 = __logf(1.0f + v0) - lgD0;
                        float li1 = __logf(1.0f + v1) - lgD1;
                        float lg0 = (z_h0 >= 0.0f) ? __logf(z_h0 + 0.5f)
                                                   : (z_h0 - __logf(1.0f + __expf(z_h0)));
                        float lg1 = (z_h1 >= 0.0f) ? __logf(z_h1 + 0.5f)
                                                   : (z_h1 - __logf(1.0f + __expf(z_h1)));
                        float lv0 = li0 + lg0;
                        float lv1 = li1 + lg1;
                        *(float2*)(g_logf + (size_t)m * DD + d0) = make_float2(lf0, lf1);
                        *(float2*)(g_lv + (size_t)(m + b + 1) * DD + d0) = make_float2(lv0, lv1);
                    }
                }
            }
        }
    }

    __syncthreads();
    if (tid == 0) {
        MBARRIER_INVAL(sb + 0);
        MBARRIER_INVAL(sb + 8);
        MBARRIER_INVAL(sb + 16);
        MBARRIER_INVAL(sb + 24);
    }
}

// =====================================================================
// a_star: feature-dim cumsum of log_f, shifted one row in time
// =====================================================================
__global__ void __launch_bounds__(256) cumsum_kernel() {
    int r = blockIdx.x;              // 0 .. B*TP1-1
    int b = r / TP1;
    int t = r - b * TP1;
    int tid = threadIdx.x;
    float4* dst = (float4*)(g_as + (size_t)r * DD);

    if (t == 0) {
        dst[tid] = make_float4(0.f, 0.f, 0.f, 0.f);
        return;
    }
    const float4* src = (const float4*)(g_logf + (size_t)(b * TT + t - 1) * DD);
    float4 v = src[tid];
    v.y += v.x; v.z += v.y; v.w += v.z;
    float tsum = v.w;

    int lane = tid & 31, warp = tid >> 5;
    #pragma unroll
    for (int off = 1; off < 32; off <<= 1) {
        float n = __shfl_up_sync(0xffffffffu, tsum, off);
        if (lane >= off) tsum += n;
    }
    __shared__ float wsum[8];
    if (lane == 31) wsum[warp] = tsum;
    __syncthreads();
    float prev = tsum - v.w;
    for (int w = 0; w < warp; w++) prev += wsum[w];
    v.x += prev; v.y += prev; v.z += prev; v.w += prev;
    dst[tid] = v;
}

// =====================================================================
// chunked logcumsumexp over time (3 passes -- proven round-12 config)
// =====================================================================
__global__ void __launch_bounds__(256) scan_a_kernel() {
    int gid = blockIdx.x * 256 + threadIdx.x;   // < CH*BD
    int c  = gid >> 13;
    int bd = gid & (BD - 1);
    int b = bd >> 10, d = bd & (DD - 1);
    int t0 = c * CS;
    int t1 = t0 + CS; if (t1 > TP1) t1 = TP1;
    size_t base = (size_t)b * TP1 * DD + d;

    float m = -INFINITY, s = 0.0f;
    for (int t = t0; t < t1; t++) {
        size_t idx = base + (size_t)t * DD;
        float v  = g_lv[idx] - g_as[idx];
        float mn = fmaxf(m, v);
        s = s * __expf(m - mn) + __expf(v - mn);
        m = mn;
    }
    g_cm[gid] = m;
    g_cs[gid] = s;
}

__global__ void __launch_bounds__(256) scan_b_kernel() {
    int bd = blockIdx.x * 256 + threadIdx.x;    // < BD
    float M = -INFINITY, S = 0.0f;
    #pragma unroll 1
    for (int c = 0; c < CH; c++) {
        int i = c * BD + bd;
        g_pm[i] = M;
        g_ps[i] = S;
        float m = g_cm[i], s = g_cs[i];
        float mn = fmaxf(M, m);
        S = S * __expf(M - mn) + s * __expf(m - mn);
        M = mn;
    }
}

__global__ void __launch_bounds__(256) scan_c_kernel(float* __restrict__ out) {
    int gid = blockIdx.x * 256 + threadIdx.x;   // < CH*BD
    int c  = gid >> 13;
    int bd = gid & (BD - 1);
    int b = bd >> 10, d = bd & (DD - 1);
    int t0 = c * CS;
    int t1 = t0 + CS; if (t1 > TP1) t1 = TP1;
    size_t base = (size_t)b * TP1 * DD + d;

    float m = g_pm[gid];
    float s = g_ps[gid];
    for (int t = t0; t < t1; t++) {
        size_t idx = base + (size_t)t * DD;
        float a  = g_as[idx];
        float v  = g_lv[idx] - a;
        float mn = fmaxf(m, v);
        s = s * __expf(m - mn) + __expf(v - mn);
        m = mn;
        out[idx] = __expf(a + m + __logf(s));
    }
}

// =====================================================================
extern "C" void kernel_launch(void* const* d_in, const int* in_sizes, int n_in,
                              void* d_out, int out_size)
{
    const float* x  = (const float*)d_in[0];
    const float* h0 = (const float*)d_in[1];
    const float* Wi = (const float*)d_in[2];
    const float* bi = (const float*)d_in[3];
    const float* Wf = (const float*)d_in[4];
    const float* bf = (const float*)d_in[5];
    const float* Wh = (const float*)d_in[6];
    const float* bh = (const float*)d_in[7];
    float* out = (float*)d_out;
    (void)in_sizes; (void)n_in; (void)out_size;

    const int smem_bytes = SMEM_TILES + 2 * STG_BYTES;   // 164864
    cudaFuncSetAttribute(gemm_kernel, cudaFuncAttributeMaxDynamicSharedMemorySize, smem_bytes);

    convert_all_kernel<<<MM + 3072 + (BB * DD) / 256, 256>>>(x, Wi, Wf, Wh, h0);
    gemm_kernel<<<PGRID, 544, smem_bytes>>>(bi, bf, bh);
    cumsum_kernel<<<BB * TP1, 256>>>();
    scan_a_kernel<<<(CH * BD) / 256, 256>>>();
    scan_b_kernel<<<BD / 256, 256>>>();
    scan_c_kernel<<<(CH * BD) / 256, 256>>>(out);
}